// round 5
// baseline (speedup 1.0000x reference)
#include <cuda_runtime.h>
#include <cstdint>

#define BB   2
#define LLEN 4096
#define KK   32
#define BLN  (BB * LLEN)   // 8192 residues
#define HALF 128
#define F_EPS 1e-6f

typedef unsigned long long ull;

// -------- scratch (device globals; no allocations allowed) --------
__device__ float g_R  [BLN * 9];
__device__ float g_t  [BLN * 3];
__device__ float g_gA [BLN * HALF];
__device__ float g_hB [BLN * HALF];

// ---- packed f32x2 helpers ----
__device__ __forceinline__ ull pack2(float lo, float hi) {
    ull r; asm("mov.b64 %0, {%1,%2};" : "=l"(r) : "f"(lo), "f"(hi)); return r;
}
__device__ __forceinline__ void unpack2(ull v, float& lo, float& hi) {
    asm("mov.b64 {%0,%1}, %2;" : "=f"(lo), "=f"(hi) : "l"(v));
}
__device__ __forceinline__ ull fma2(ull a, ull b, ull c) {
    ull d; asm("fma.rn.f32x2 %0, %1, %2, %3;" : "=l"(d) : "l"(a), "l"(b), "l"(c)); return d;
}
__device__ __forceinline__ ull mul2(ull a, ull b) {
    ull d; asm("mul.rn.f32x2 %0, %1, %2;" : "=l"(d) : "l"(a), "l"(b)); return d;
}
__device__ __forceinline__ ull add2(ull a, ull b) {
    ull d; asm("add.rn.f32x2 %0, %1, %2;" : "=l"(d) : "l"(a), "l"(b)); return d;
}

// -------- phase 1: per-residue frames + intra partial sums (W prep fused) --------
__global__ void k_residue(const float* __restrict__ X, const int* __restrict__ Cm,
                          const float* __restrict__ Wd) {
    int bl = blockIdx.x;
    int e  = threadIdx.x;
    __shared__ float sXi[12];
    if (e < 12) sXi[e] = X[bl * 12 + e];
    __syncthreads();

    float N0 = sXi[0], N1 = sXi[1],  N2 = sXi[2];
    float A0 = sXi[3], A1 = sXi[4],  A2 = sXi[5];
    float C0 = sXi[6], C1 = sXi[7],  C2 = sXi[8];

    float v0 = N0 - A0, v1 = N1 - A1, v2 = N2 - A2;
    float inv = 1.0f / (sqrtf(v0 * v0 + v1 * v1 + v2 * v2) + F_EPS);
    float e10 = v0 * inv, e11 = v1 * inv, e12 = v2 * inv;
    float u0 = C0 - A0, u1 = C1 - A1, u2 = C2 - A2;
    inv = 1.0f / (sqrtf(u0 * u0 + u1 * u1 + u2 * u2) + F_EPS);
    u0 *= inv; u1 *= inv; u2 *= inv;
    float d  = u0 * e10 + u1 * e11 + u2 * e12;
    float w0 = u0 - d * e10, w1 = u1 - d * e11, w2 = u2 - d * e12;
    inv = 1.0f / (sqrtf(w0 * w0 + w1 * w1 + w2 * w2) + F_EPS);
    float e20 = w0 * inv, e21 = w1 * inv, e22 = w2 * inv;
    float e30 = e11 * e22 - e12 * e21;
    float e31 = e12 * e20 - e10 * e22;
    float e32 = e10 * e21 - e11 * e20;

    float mask = (Cm[bl] > 0) ? 1.0f : 0.0f;

    if (e == 0) {
        g_R[bl * 9 + 0] = e10 * mask; g_R[bl * 9 + 1] = e20 * mask; g_R[bl * 9 + 2] = e30 * mask;
        g_R[bl * 9 + 3] = e11 * mask; g_R[bl * 9 + 4] = e21 * mask; g_R[bl * 9 + 5] = e31 * mask;
        g_R[bl * 9 + 6] = e12 * mask; g_R[bl * 9 + 7] = e22 * mask; g_R[bl * 9 + 8] = e32 * mask;
        g_t[bl * 3 + 0] = A0 * mask;  g_t[bl * 3 + 1] = A1 * mask;  g_t[bl * 3 + 2] = A2 * mask;
    }

    const int pa[6] = {0, 0, 0, 1, 1, 2};
    const int pb[6] = {1, 2, 3, 2, 3, 3};
    float d6[6];
#pragma unroll
    for (int u = 0; u < 6; u++) {
        int a = pa[u] * 3, b = pb[u] * 3;
        float dx = sXi[a + 0] - sXi[b + 0];
        float dy = sXi[a + 1] - sXi[b + 1];
        float dz = sXi[a + 2] - sXi[b + 2];
        d6[u] = sqrtf(fmaf(dx, dx, fmaf(dy, dy, fmaf(dz, dz, F_EPS))));
    }
    float cw = 0.f;
#pragma unroll
    for (int a = 0; a < 8; a++) cw += Wd[(a * 8 + a) * HALF + e];
    float gA = cw * sqrtf(F_EPS);
    float hB = 0.f;
#pragma unroll
    for (int u = 0; u < 6; u++) {
        int a = pa[u], b = pb[u];
        float wA = Wd[(a * 8 + b) * HALF + e] + Wd[(b * 8 + a) * HALF + e];
        float wB = Wd[((a + 4) * 8 + (b + 4)) * HALF + e]
                 + Wd[((b + 4) * 8 + (a + 4)) * HALF + e];
        gA = fmaf(d6[u], wA, gA);
        hB = fmaf(d6[u], wB, hB);
    }
    g_gA[bl * HALF + e] = gA;
    g_hB[bl * HALF + e] = hB;
}

// -------- phase 2: per-edge fourier features, edge-pair packed --------
__global__ __launch_bounds__(128) void k_edges(
    const float* __restrict__ X,
    const int*   __restrict__ eidx,
    const float* __restrict__ Wvec,
    const float* __restrict__ Wd,
    float*       __restrict__ out)
{
    int bl = blockIdx.x;
    int e  = threadIdx.x;                      // output channel 0..127
    int b  = bl >> 12;                         // L = 4096

    __shared__ float sXi[12], sR[9], st[3];
    __shared__ int   sjb[KK];
    __shared__ float sXj[KK][12];
    __shared__ __align__(8) float sDt[16][KK]; // cross distances, c-major (edge pairs adjacent)
    __shared__ __align__(8) float sTt[3][KK];  // t_ji, component-major
    __shared__ float sHB[KK][HALF];            // neighbor hB rows (bulk preloaded)

    if (e < 12) sXi[e] = X[bl * 12 + e];
    if (e < 9)  sR[e]  = g_R[bl * 9 + e];
    if (e < 3)  st[e]  = g_t[bl * 3 + e];
    if (e < KK) sjb[e] = (b << 12) + eidx[bl * KK + e];
    __syncthreads();

    // neighbor coords: 32*12 = 384 floats, 3 per thread
#pragma unroll
    for (int i = 0; i < 3; i++) {
        int idx = e + i * 128;
        int n = idx / 12, c = idx - n * 12;
        sXj[n][c] = X[(size_t)sjb[n] * 12 + c];
    }
    // t_ji per neighbor (threads 0..31)
    if (e < KK) {
        int jb = sjb[e];
        float dt0 = g_t[jb * 3 + 0] - st[0];
        float dt1 = g_t[jb * 3 + 1] - st[1];
        float dt2 = g_t[jb * 3 + 2] - st[2];
        sTt[0][e] = sR[0] * dt0 + sR[3] * dt1 + sR[6] * dt2;
        sTt[1][e] = sR[1] * dt0 + sR[4] * dt1 + sR[7] * dt2;
        sTt[2][e] = sR[2] * dt0 + sR[5] * dt1 + sR[8] * dt2;
    }
    // bulk preload of all neighbor hB rows (coalesced, high MLP)
#pragma unroll 8
    for (int n = 0; n < KK; n++)
        sHB[n][e] = g_hB[(size_t)sjb[n] * HALF + e];
    __syncthreads();

    // all 512 cross distances, stored transposed: sDt[pq][n]
#pragma unroll
    for (int i = 0; i < 4; i++) {
        int idx = e * 4 + i;
        int n = idx >> 4, pq = idx & 15;
        int p = (pq >> 2) * 3, q = (pq & 3) * 3;
        float dx = sXi[p + 0] - sXj[n][q + 0];
        float dy = sXi[p + 1] - sXj[n][q + 1];
        float dz = sXi[p + 2] - sXj[n][q + 2];
        sDt[pq][n] = sqrtf(fmaf(dx, dx, fmaf(dy, dy, fmaf(dz, dz, F_EPS))));
    }

    // per-thread invariants
    float gA = g_gA[bl * HALF + e];
    ull Wv0 = pack2(Wvec[e], Wvec[e]);
    ull Wv1 = pack2(Wvec[HALF + e], Wvec[HALF + e]);
    ull Wv2 = pack2(Wvec[2 * HALF + e], Wvec[2 * HALF + e]);
    ull Wc2[16];
#pragma unroll
    for (int p = 0; p < 4; p++)
#pragma unroll
        for (int q = 0; q < 4; q++) {
            float w = Wd[(p * 8 + q + 4) * HALF + e] + Wd[((q + 4) * 8 + p) * HALF + e];
            Wc2[p * 4 + q] = pack2(w, w);
        }

    // packed constants
    const ull TWO2 = pack2(2.0f, 2.0f);
    const ull MAG2 = pack2(12582912.0f, 12582912.0f);    // 1.5 * 2^23
    const ull NMAG2 = pack2(-12582912.0f, -12582912.0f);
    const ull NH2  = pack2(-0.5f, -0.5f);
    const ull CC4 = pack2( 60.2446414f,  60.2446414f);
    const ull CC3 = pack2(-85.4568172f, -85.4568172f);
    const ull CC2 = pack2( 64.9393940f,  64.9393940f);
    const ull CC1 = pack2(-19.7392088f, -19.7392088f);
    const ull CC0 = pack2(  1.0f,         1.0f);
    const ull SS4 = pack2( 42.0586939f,  42.0586939f);
    const ull SS3 = pack2(-76.7058598f, -76.7058598f);
    const ull SS2 = pack2( 81.6052493f,  81.6052493f);
    const ull SS1 = pack2(-41.3417022f, -41.3417022f);
    const ull SS0 = pack2(  6.28318531f,  6.28318531f);

    __syncthreads();

    // --- pure-compute loop, two edges per iteration (f32x2 lanes = edges) ---
    size_t ob = (size_t)bl * KK * 256;
#pragma unroll 2
    for (int k = 0; k < KK; k += 2) {
        // yd for both edges: gA + hB_j + 16-term cross dot
        ull acc = pack2(gA + sHB[k][e], gA + sHB[k + 1][e]);
#pragma unroll
        for (int c = 0; c < 16; c++)
            acc = fma2(*(const ull*)&sDt[c][k], Wc2[c], acc);
        ull yd2 = acc;

        // yv for both edges
        ull yv2 = fma2(*(const ull*)&sTt[0][k], Wv0,
                  fma2(*(const ull*)&sTt[1][k], Wv1,
                  mul2(*(const ull*)&sTt[2][k], Wv2)));

        // range reduction via magic number: f = rn(2y + 1.5*2^23)
        ull fv = fma2(yv2, TWO2, MAG2);
        ull fd = fma2(yd2, TWO2, MAG2);
        ull rv = add2(fv, NMAG2);               // = round(2y) exactly
        ull rd = add2(fd, NMAG2);
        ull gv = fma2(rv, NH2, yv2);            // |g| <= 0.25
        ull gd = fma2(rd, NH2, yd2);

        ull tv = mul2(gv, gv);
        ull td = mul2(gd, gd);
        ull cpv = fma2(CC4, tv, CC3); cpv = fma2(cpv, tv, CC2);
        cpv = fma2(cpv, tv, CC1);     cpv = fma2(cpv, tv, CC0);
        ull cpd = fma2(CC4, td, CC3); cpd = fma2(cpd, td, CC2);
        cpd = fma2(cpd, td, CC1);     cpd = fma2(cpd, td, CC0);
        ull spv = fma2(SS4, tv, SS3); spv = fma2(spv, tv, SS2);
        spv = fma2(spv, tv, SS1);     spv = fma2(spv, tv, SS0);
        spv = mul2(spv, gv);
        ull spd = fma2(SS4, td, SS3); spd = fma2(spd, td, SS2);
        spd = fma2(spd, td, SS1);     spd = fma2(spd, td, SS0);
        spd = mul2(spd, gd);

        // sign flip by parity of round(2y): bit0 of the magic float's payload
        ull mv = ((ull)(((unsigned)fv) & 1u) << 31) | ((ull)(((unsigned)(fv >> 32)) & 1u) << 63);
        ull md = ((ull)(((unsigned)fd) & 1u) << 31) | ((ull)(((unsigned)(fd >> 32)) & 1u) << 63);
        cpv ^= mv; spv ^= mv;
        cpd ^= md; spd ^= md;

        ull cs = add2(cpv, cpd);                // cos(vec)+cos(dist), both edges
        ull ss = add2(spv, spd);                // sin(vec)+sin(dist), both edges

        float c0, c1, s0, s1;
        unpack2(cs, c0, c1);
        unpack2(ss, s0, s1);
        out[ob + e]              = c0;
        out[ob + HALF + e]       = s0;
        out[ob + 256 + e]        = c1;
        out[ob + 256 + HALF + e] = s1;
        ob += 512;
    }
}

extern "C" void kernel_launch(void* const* d_in, const int* in_sizes, int n_in,
                              void* d_out, int out_size)
{
    const float* X    = (const float*)d_in[0];   // (B,L,4,3) f32
    const int*   eix  = (const int*)  d_in[1];   // (B,L,K) i32
    const int*   Cm   = (const int*)  d_in[2];   // (B,L) i32
    const float* Wvec = (const float*)d_in[3];   // (3,128) f32
    const float* Wd   = (const float*)d_in[4];   // (64,128) f32
    float* out = (float*)d_out;

    k_residue<<<BLN, 128>>>(X, Cm, Wd);
    k_edges<<<BLN, 128>>>(X, eix, Wvec, Wd, out);
}